// round 1
// baseline (speedup 1.0000x reference)
#include <cuda_runtime.h>
#include <cstdint>

#define K_DIM 8192
#define M_DIM 8192
#define N_DIM 8
#define KSPLIT 32
#define CHUNK (K_DIM / KSPLIT)      // 256
#define ROWS_PER_BLOCK 256          // 4 warps * 64 rows
#define GEMV_THREADS 128

// ---------------- static device scratch (no runtime allocation) ----------------
__device__ float4 g_xt4[K_DIM * 2];                          // x_hat transposed [K][8] (256 KB)
__device__ float g_bsum[1024];                               // per-block |W| partial sums
__device__ float g_thresh;                                   // 0.5 * w_deq
__device__ float g_wdeq;                                     // 1/s_w
__device__ unsigned long long g_part[M_DIM * KSPLIT * 4];    // K-split partials, f32x2 packed (8 MB)

// ---------------- helpers ----------------
__device__ __forceinline__ void fma2(unsigned long long& acc, unsigned long long x,
                                     unsigned long long q) {
    asm("fma.rn.f32x2 %0, %1, %2, %0;" : "+l"(acc) : "l"(x), "l"(q));
}

__device__ __forceinline__ unsigned long long qpack(float w, float t) {
    // ternary quant: q = sign(w) if |w| > t else 0 ; packed as (q, q) f32x2
    float q = (fabsf(w) > t) ? 1.0f : 0.0f;
    q = copysignf(q, w);
    unsigned long long q2;
    asm("mov.b64 %0, {%1, %1};" : "=l"(q2) : "f"(q));
    return q2;
}

// ---------------- kernel 1: activation per-group int8 quantization ----------------
// groups of 64 along K, per row. One warp per group. Output transposed [K][8].
__global__ void quant_x_kernel(const float* __restrict__ x) {
    int gw = (blockIdx.x * blockDim.x + threadIdx.x) >> 5;   // global warp 0..1023
    int lane = threadIdx.x & 31;
    int n = gw >> 7;          // 0..7
    int g = gw & 127;         // 0..127
    int k0 = g * 64 + lane;
    float a = x[n * K_DIM + k0];
    float b = x[n * K_DIM + k0 + 32];
    float mx = fmaxf(fabsf(a), fabsf(b));
#pragma unroll
    for (int off = 16; off; off >>= 1)
        mx = fmaxf(mx, __shfl_xor_sync(0xffffffffu, mx, off));
    float s = fmaxf(__fdiv_rn(mx, 127.0f), 1e-8f);           // matches jnp: div then clamp
    float ah = rintf(__fdiv_rn(a, s)) * s;                   // rintf = round half-to-even
    float bh = rintf(__fdiv_rn(b, s)) * s;
    float* xt = (float*)g_xt4;
    xt[k0 * 8 + n] = ah;
    xt[(k0 + 32) * 8 + n] = bh;
}

// ---------------- kernel 2: sum |W| partials (streaming 256 MB) ----------------
__global__ void absmean_kernel(const float4* __restrict__ W4) {
    __shared__ float sm[8];
    float s = 0.f;
    int stride = gridDim.x * blockDim.x;
    for (int i = blockIdx.x * blockDim.x + threadIdx.x; i < (K_DIM * M_DIM) / 4; i += stride) {
        float4 v = __ldg(W4 + i);
        s += fabsf(v.x) + fabsf(v.y) + fabsf(v.z) + fabsf(v.w);
    }
#pragma unroll
    for (int off = 16; off; off >>= 1) s += __shfl_xor_sync(0xffffffffu, s, off);
    int lane = threadIdx.x & 31, w = threadIdx.x >> 5;
    if (lane == 0) sm[w] = s;
    __syncthreads();
    if (threadIdx.x == 0) {
        float tot = 0.f;
#pragma unroll
        for (int i = 0; i < 8; i++) tot += sm[i];
        g_bsum[blockIdx.x] = tot;
    }
}

// ---------------- kernel 3: finalize mean -> threshold & dequant scale ----------------
__global__ void finalize_mean_kernel() {
    __shared__ float sm[8];
    int tid = threadIdx.x;
    float s = g_bsum[tid] + g_bsum[tid + 256] + g_bsum[tid + 512] + g_bsum[tid + 768];
#pragma unroll
    for (int off = 16; off; off >>= 1) s += __shfl_xor_sync(0xffffffffu, s, off);
    int lane = tid & 31, w = tid >> 5;
    if (lane == 0) sm[w] = s;
    __syncthreads();
    if (tid == 0) {
        float tot = 0.f;
#pragma unroll
        for (int i = 0; i < 8; i++) tot += sm[i];
        float mean = tot * (1.0f / 67108864.0f);             // /2^26 exact
        float m = fmaxf(mean, 1e-5f);                        // jnp.clip(mean, 1e-5, None)
        float s_w = __fdiv_rn(1.0f, m);
        float wdeq = __fdiv_rn(1.0f, s_w);                   // 1/s_w as in reference
        g_wdeq = wdeq;
        g_thresh = 0.5f * wdeq;                              // |w| > t  <=>  |w*s_w| > 0.5
    }
}

// ---------------- kernel 4: fused ternary-quant GEMV, K split 32 ways ----------------
// Each lane owns rows r0 and r0+32 (full private accumulators -> no reductions).
// x_hat loads are warp-uniform broadcasts; W loads are per-lane row streams.
__global__ __launch_bounds__(GEMV_THREADS) void gemv_kernel(const float* __restrict__ W) {
    const float t = g_thresh;
    int lane = threadIdx.x & 31, warp = threadIdx.x >> 5;
    int mb = blockIdx.x >> 5;                 // 0..31
    int ks = blockIdx.x & 31;                 // 0..31
    int r0 = mb * ROWS_PER_BLOCK + warp * 64 + lane;   // rows r0 and r0+32
    int k0 = ks * CHUNK;

    const float4* Wa = (const float4*)(W + (size_t)r0 * K_DIM + k0);
    const float4* Wb = (const float4*)(W + (size_t)(r0 + 32) * K_DIM + k0);
    const ulonglong2* X = (const ulonglong2*)g_xt4 + (size_t)k0 * 2;

    unsigned long long a0 = 0, a1 = 0, a2 = 0, a3 = 0;
    unsigned long long b0 = 0, b1 = 0, b2 = 0, b3 = 0;

#pragma unroll 2
    for (int i = 0; i < CHUNK / 4; i++) {
        float4 wa = __ldg(Wa + i);
        float4 wb = __ldg(Wb + i);
        float wae[4] = {wa.x, wa.y, wa.z, wa.w};
        float wbe[4] = {wb.x, wb.y, wb.z, wb.w};
#pragma unroll
        for (int e = 0; e < 4; e++) {
            ulonglong2 x0 = X[(i * 4 + e) * 2];        // x_hat[k][0..3]
            ulonglong2 x1 = X[(i * 4 + e) * 2 + 1];    // x_hat[k][4..7]
            unsigned long long qa = qpack(wae[e], t);
            unsigned long long qb = qpack(wbe[e], t);
            fma2(a0, x0.x, qa); fma2(a1, x0.y, qa);
            fma2(a2, x1.x, qa); fma2(a3, x1.y, qa);
            fma2(b0, x0.x, qb); fma2(b1, x0.y, qb);
            fma2(b2, x1.x, qb); fma2(b3, x1.y, qb);
        }
    }

    ulonglong2* P = (ulonglong2*)g_part;
    size_t pa = ((size_t)r0 * KSPLIT + ks) * 2;
    size_t pb = ((size_t)(r0 + 32) * KSPLIT + ks) * 2;
    P[pa]     = make_ulonglong2(a0, a1);
    P[pa + 1] = make_ulonglong2(a2, a3);
    P[pb]     = make_ulonglong2(b0, b1);
    P[pb + 1] = make_ulonglong2(b2, b3);
}

// ---------------- kernel 5: reduce K-split partials, apply w_deq, write [N, M] ----------------
__global__ void finalize_out_kernel(float* __restrict__ out) {
    int m = blockIdx.x * blockDim.x + threadIdx.x;     // 0..8191
    const float4* p = (const float4*)g_part + (size_t)m * KSPLIT * 2;
    float s0 = 0, s1 = 0, s2 = 0, s3 = 0, s4 = 0, s5 = 0, s6 = 0, s7 = 0;
#pragma unroll
    for (int ks = 0; ks < KSPLIT; ks++) {
        float4 A = p[ks * 2];
        float4 B = p[ks * 2 + 1];
        s0 += A.x; s1 += A.y; s2 += A.z; s3 += A.w;
        s4 += B.x; s5 += B.y; s6 += B.z; s7 += B.w;
    }
    float wd = g_wdeq;
    out[0 * M_DIM + m] = wd * s0;
    out[1 * M_DIM + m] = wd * s1;
    out[2 * M_DIM + m] = wd * s2;
    out[3 * M_DIM + m] = wd * s3;
    out[4 * M_DIM + m] = wd * s4;
    out[5 * M_DIM + m] = wd * s5;
    out[6 * M_DIM + m] = wd * s6;
    out[7 * M_DIM + m] = wd * s7;
}

// ---------------- launch ----------------
extern "C" void kernel_launch(void* const* d_in, const int* in_sizes, int n_in,
                              void* d_out, int out_size) {
    const float* x = (const float*)d_in[0];    // [8, 8192]
    const float* W = (const float*)d_in[1];    // [8192, 8192]
    float* out = (float*)d_out;                // [8, 8192]

    quant_x_kernel<<<128, 256>>>(x);                       // x -> x_hat (transposed)
    absmean_kernel<<<1024, 256>>>((const float4*)W);       // pass 1 over W
    finalize_mean_kernel<<<1, 256>>>();                    // scalar: s_w, w_deq, t
    gemv_kernel<<<1024, GEMV_THREADS>>>(W);                // pass 2 over W (fused quant+GEMV)
    finalize_out_kernel<<<64, 128>>>(out);                 // K-split reduce + scale
}

// round 2
// speedup vs baseline: 1.2918x; 1.2918x over previous
#include <cuda_runtime.h>
#include <cstdint>

#define K_DIM 8192
#define M_DIM 8192
#define N_DIM 8

// gemv tiling
#define ROWTILE 64
#define KC 8                       // k-chunks per row
#define CHUNK (K_DIM / KC)         // 1024
#define SLICE_K 128                // k's per staged slice
#define NSLICES (CHUNK / SLICE_K)  // 8
#define PARTS (KC * 8)             // 64 partials per row (8 warps per block)
// smem: per buffer: W 64*128 floats (32KB) + X 128*8 floats (4KB) = 9216 floats
#define BUF_FLOATS 9216
#define SMEM_BYTES (2 * BUF_FLOATS * 4)

// ---------------- static device scratch ----------------
__device__ float4 g_xt4[K_DIM * 2];                         // x_hat transposed [K][8] (256 KB)
__device__ float g_bsum[1024];
__device__ float g_thresh;
__device__ float g_wdeq;
__device__ unsigned long long g_part[(size_t)M_DIM * PARTS * 4];  // 16 MB, f32x2-packed

// ---------------- helpers ----------------
__device__ __forceinline__ void fma2(unsigned long long& acc, unsigned long long x,
                                     unsigned long long q) {
    asm("fma.rn.f32x2 %0, %1, %2, %0;" : "+l"(acc) : "l"(x), "l"(q));
}

__device__ __forceinline__ unsigned long long qpack(float w, float t) {
    float q = (fabsf(w) > t) ? 1.0f : 0.0f;
    q = copysignf(q, w);
    unsigned long long q2;
    asm("mov.b64 %0, {%1, %1};" : "=l"(q2) : "f"(q));
    return q2;
}

__device__ __forceinline__ void cpasync16(void* smem_dst, const void* gsrc) {
    unsigned int sa = (unsigned int)__cvta_generic_to_shared(smem_dst);
    asm volatile("cp.async.cg.shared.global [%0], [%1], 16;" :: "r"(sa), "l"(gsrc));
}
__device__ __forceinline__ void cp_commit() {
    asm volatile("cp.async.commit_group;");
}
__device__ __forceinline__ void cp_wait1() {
    asm volatile("cp.async.wait_group 1;");
}

// ---------------- kernel 1: activation per-group int8 quantization ----------------
__global__ void quant_x_kernel(const float* __restrict__ x) {
    int gw = (blockIdx.x * blockDim.x + threadIdx.x) >> 5;
    int lane = threadIdx.x & 31;
    int n = gw >> 7;
    int g = gw & 127;
    int k0 = g * 64 + lane;
    float a = x[n * K_DIM + k0];
    float b = x[n * K_DIM + k0 + 32];
    float mx = fmaxf(fabsf(a), fabsf(b));
#pragma unroll
    for (int off = 16; off; off >>= 1)
        mx = fmaxf(mx, __shfl_xor_sync(0xffffffffu, mx, off));
    float s = fmaxf(__fdiv_rn(mx, 127.0f), 1e-8f);
    float ah = rintf(__fdiv_rn(a, s)) * s;
    float bh = rintf(__fdiv_rn(b, s)) * s;
    float* xt = (float*)g_xt4;
    xt[k0 * 8 + n] = ah;
    xt[(k0 + 32) * 8 + n] = bh;
}

// ---------------- kernel 2: sum |W| partials, 4-way MLP unrolled ----------------
__global__ void absmean_kernel(const float4* __restrict__ W4) {
    __shared__ float sm[8];
    const int stride = 1024 * 256;
    int t = blockIdx.x * 256 + threadIdx.x;
    const float4* p = W4 + t;
    float s0 = 0.f, s1 = 0.f, s2 = 0.f, s3 = 0.f;
#pragma unroll 4
    for (int it = 0; it < 64; it += 4) {
        float4 a = __ldg(p + (size_t)(it + 0) * stride);
        float4 b = __ldg(p + (size_t)(it + 1) * stride);
        float4 c = __ldg(p + (size_t)(it + 2) * stride);
        float4 d = __ldg(p + (size_t)(it + 3) * stride);
        s0 += fabsf(a.x) + fabsf(a.y) + fabsf(a.z) + fabsf(a.w);
        s1 += fabsf(b.x) + fabsf(b.y) + fabsf(b.z) + fabsf(b.w);
        s2 += fabsf(c.x) + fabsf(c.y) + fabsf(c.z) + fabsf(c.w);
        s3 += fabsf(d.x) + fabsf(d.y) + fabsf(d.z) + fabsf(d.w);
    }
    float s = (s0 + s1) + (s2 + s3);
#pragma unroll
    for (int off = 16; off; off >>= 1) s += __shfl_xor_sync(0xffffffffu, s, off);
    int lane = threadIdx.x & 31, w = threadIdx.x >> 5;
    if (lane == 0) sm[w] = s;
    __syncthreads();
    if (threadIdx.x == 0) {
        float tot = 0.f;
#pragma unroll
        for (int i = 0; i < 8; i++) tot += sm[i];
        g_bsum[blockIdx.x] = tot;
    }
}

// ---------------- kernel 3: finalize mean ----------------
__global__ void finalize_mean_kernel() {
    __shared__ float sm[8];
    int tid = threadIdx.x;
    float s = g_bsum[tid] + g_bsum[tid + 256] + g_bsum[tid + 512] + g_bsum[tid + 768];
#pragma unroll
    for (int off = 16; off; off >>= 1) s += __shfl_xor_sync(0xffffffffu, s, off);
    int lane = tid & 31, w = tid >> 5;
    if (lane == 0) sm[w] = s;
    __syncthreads();
    if (tid == 0) {
        float tot = 0.f;
#pragma unroll
        for (int i = 0; i < 8; i++) tot += sm[i];
        float mean = tot * (1.0f / 67108864.0f);
        float m = fmaxf(mean, 1e-5f);
        float s_w = __fdiv_rn(1.0f, m);
        float wdeq = __fdiv_rn(1.0f, s_w);
        g_wdeq = wdeq;
        g_thresh = 0.5f * wdeq;
    }
}

// ---------------- kernel 4: fused ternary GEMV with cp.async smem staging ----------------
// Block: 64 rows x 1024-k chunk; 8 warps each own a 16-k lane of every 128-k slice.
// Lane owns rows (lane, lane+32): x is warp-uniform, no cross-lane reductions.
// W staged in smem with 16B XOR swizzle (chunk ^ (row & 7)) -> conflict-free LDS.128.
__global__ __launch_bounds__(256) void gemv_kernel(const float* __restrict__ W) {
    extern __shared__ float smem[];
    const float t = g_thresh;
    const int tid = threadIdx.x;
    const int lane = tid & 31, warp = tid >> 5;
    const int rt = blockIdx.x >> 3;            // 0..127 row tiles
    const int kc = blockIdx.x & 7;             // 0..7 k chunks
    const int rowbase = rt * ROWTILE;
    const int k0 = kc * CHUNK;

    // stage slice s into buffer b
    auto stage = [&](int s, int b) {
        float* bufW = smem + b * BUF_FLOATS;
        float* bufX = bufW + ROWTILE * SLICE_K;
        int base_k = k0 + s * SLICE_K;
#pragma unroll
        for (int idx = tid; idx < 2304; idx += 256) {
            if (idx < 2048) {
                int r = idx >> 5, c = idx & 31;
                const float* src = W + (size_t)(rowbase + r) * K_DIM + base_k + c * 4;
                float* dst = bufW + r * SLICE_K + ((c ^ (r & 7)) << 2);
                cpasync16(dst, src);
            } else {
                int j = idx - 2048;  // 0..255
                const float* src = ((const float*)g_xt4) + (size_t)base_k * 8 + j * 4;
                cpasync16(bufX + j * 4, src);
            }
        }
    };

    unsigned long long a0 = 0, a1 = 0, a2 = 0, a3 = 0;
    unsigned long long b0 = 0, b1 = 0, b2 = 0, b3 = 0;

    stage(0, 0);
    cp_commit();

    for (int s = 0; s < NSLICES; s++) {
        if (s + 1 < NSLICES) stage(s + 1, (s + 1) & 1);
        cp_commit();
        cp_wait1();
        __syncthreads();

        const float* bufW = smem + (s & 1) * BUF_FLOATS;
        const ulonglong2* Xb = (const ulonglong2*)(bufW + ROWTILE * SLICE_K);
        const int sw = lane & 7;
#pragma unroll
        for (int step = 0; step < 4; step++) {
            int kk = warp * 16 + step * 4;       // slice-local float-k
            int ch = kk >> 2;
            float4 wa = *(const float4*)(bufW + lane * SLICE_K + ((ch ^ sw) << 2));
            float4 wb = *(const float4*)(bufW + (lane + 32) * SLICE_K + ((ch ^ sw) << 2));
            float wae[4] = {wa.x, wa.y, wa.z, wa.w};
            float wbe[4] = {wb.x, wb.y, wb.z, wb.w};
#pragma unroll
            for (int e = 0; e < 4; e++) {
                ulonglong2 x0 = Xb[(kk + e) * 2];
                ulonglong2 x1 = Xb[(kk + e) * 2 + 1];
                unsigned long long qa = qpack(wae[e], t);
                unsigned long long qb = qpack(wbe[e], t);
                fma2(a0, x0.x, qa); fma2(a1, x0.y, qa);
                fma2(a2, x1.x, qa); fma2(a3, x1.y, qa);
                fma2(b0, x0.x, qb); fma2(b1, x0.y, qb);
                fma2(b2, x1.x, qb); fma2(b3, x1.y, qb);
            }
        }
        __syncthreads();
    }

    // write partials: slot index p = kc*8 + warp
    ulonglong2* P = (ulonglong2*)g_part;
    int p = kc * 8 + warp;
    size_t pa = ((size_t)(rowbase + lane) * PARTS + p) * 2;
    size_t pb = ((size_t)(rowbase + lane + 32) * PARTS + p) * 2;
    P[pa]     = make_ulonglong2(a0, a1);
    P[pa + 1] = make_ulonglong2(a2, a3);
    P[pb]     = make_ulonglong2(b0, b1);
    P[pb + 1] = make_ulonglong2(b2, b3);
}

// ---------------- kernel 5: reduce partials, apply w_deq ----------------
__global__ void finalize_out_kernel(float* __restrict__ out) {
    int m = blockIdx.x * blockDim.x + threadIdx.x;
    const float4* p = (const float4*)g_part + (size_t)m * PARTS * 2;
    float s0 = 0, s1 = 0, s2 = 0, s3 = 0, s4 = 0, s5 = 0, s6 = 0, s7 = 0;
#pragma unroll 8
    for (int ks = 0; ks < PARTS; ks++) {
        float4 A = p[ks * 2];
        float4 B = p[ks * 2 + 1];
        s0 += A.x; s1 += A.y; s2 += A.z; s3 += A.w;
        s4 += B.x; s5 += B.y; s6 += B.z; s7 += B.w;
    }
    float wd = g_wdeq;
    out[0 * M_DIM + m] = wd * s0;
    out[1 * M_DIM + m] = wd * s1;
    out[2 * M_DIM + m] = wd * s2;
    out[3 * M_DIM + m] = wd * s3;
    out[4 * M_DIM + m] = wd * s4;
    out[5 * M_DIM + m] = wd * s5;
    out[6 * M_DIM + m] = wd * s6;
    out[7 * M_DIM + m] = wd * s7;
}

// ---------------- launch ----------------
extern "C" void kernel_launch(void* const* d_in, const int* in_sizes, int n_in,
                              void* d_out, int out_size) {
    const float* x = (const float*)d_in[0];    // [8, 8192]
    const float* W = (const float*)d_in[1];    // [8192, 8192]
    float* out = (float*)d_out;                // [8, 8192]

    static bool attr_done = false;
    if (!attr_done) {
        cudaFuncSetAttribute(gemv_kernel, cudaFuncAttributeMaxDynamicSharedMemorySize,
                             SMEM_BYTES);
        attr_done = true;
    }

    quant_x_kernel<<<128, 256>>>(x);
    absmean_kernel<<<1024, 256>>>((const float4*)W);
    finalize_mean_kernel<<<1, 256>>>();
    gemv_kernel<<<1024, 256, SMEM_BYTES>>>(W);
    finalize_out_kernel<<<64, 128>>>(out);
}

// round 3
// speedup vs baseline: 1.6630x; 1.2873x over previous
#include <cuda_runtime.h>
#include <cstdint>

#define K_DIM 8192
#define M_DIM 8192
#define N_DIM 8

// gemv tiling
#define ROWTILE 64
#define KC 4                        // k-chunks per row
#define CHUNK (K_DIM / KC)          // 2048
#define SLICE_K 64                  // k's per staged slice
#define NSLICES (CHUNK / SLICE_K)   // 32
// per buffer: W 64*64 floats (16KB) + X 64*8 floats (2KB) = 4608 floats
#define BUF_FLOATS 4608
#define NBUF 3
#define SMEM_BYTES (NBUF * BUF_FLOATS * 4)   // 55296

typedef unsigned long long ull;

// ---------------- static device scratch ----------------
__device__ float4 g_xt4[K_DIM * 2];            // x_hat transposed [K][8] (256 KB)
__device__ float g_bsum[1024];
__device__ float g_thresh;
__device__ float g_wdeq;
__device__ ull g_part[(size_t)M_DIM * KC * 4]; // 1 MB, f32x2-packed

// ---------------- helpers ----------------
__device__ __forceinline__ void fma2(ull& acc, ull x, ull q) {
    asm("fma.rn.f32x2 %0, %1, %2, %0;" : "+l"(acc) : "l"(x), "l"(q));
}
__device__ __forceinline__ void add2(ull& acc, ull x) {
    asm("add.rn.f32x2 %0, %1, %0;" : "+l"(acc) : "l"(x));
}
__device__ __forceinline__ ull qpack(float w, float t) {
    float q = (fabsf(w) > t) ? 1.0f : 0.0f;
    q = copysignf(q, w);
    ull q2;
    asm("mov.b64 %0, {%1, %1};" : "=l"(q2) : "f"(q));
    return q2;
}
__device__ __forceinline__ void cpasync16(void* smem_dst, const void* gsrc) {
    unsigned int sa = (unsigned int)__cvta_generic_to_shared(smem_dst);
    asm volatile("cp.async.cg.shared.global [%0], [%1], 16;" :: "r"(sa), "l"(gsrc));
}
__device__ __forceinline__ void cp_commit() { asm volatile("cp.async.commit_group;"); }
__device__ __forceinline__ void cp_wait1()  { asm volatile("cp.async.wait_group 1;"); }

// ---------------- kernel 1: activation per-group int8 quantization ----------------
__global__ void quant_x_kernel(const float* __restrict__ x) {
    int gw = (blockIdx.x * blockDim.x + threadIdx.x) >> 5;
    int lane = threadIdx.x & 31;
    int n = gw >> 7;
    int g = gw & 127;
    int k0 = g * 64 + lane;
    float a = x[n * K_DIM + k0];
    float b = x[n * K_DIM + k0 + 32];
    float mx = fmaxf(fabsf(a), fabsf(b));
#pragma unroll
    for (int off = 16; off; off >>= 1)
        mx = fmaxf(mx, __shfl_xor_sync(0xffffffffu, mx, off));
    float s = fmaxf(__fdiv_rn(mx, 127.0f), 1e-8f);
    float ah = rintf(__fdiv_rn(a, s)) * s;
    float bh = rintf(__fdiv_rn(b, s)) * s;
    float* xt = (float*)g_xt4;
    xt[k0 * 8 + n] = ah;
    xt[(k0 + 32) * 8 + n] = bh;
}

// ---------------- kernel 2: sum |W| — BIT-EXACT round-1 accumulation order ----------------
// (single accumulator, same element sequence; loads prefetched 4-deep for MLP)
__global__ void absmean_kernel(const float4* __restrict__ W4) {
    __shared__ float sm[8];
    const int stride = 1024 * 256;
    int t0 = blockIdx.x * 256 + threadIdx.x;
    const float4* p = W4 + t0;
    float s = 0.f;
#pragma unroll 2
    for (int it = 0; it < 64; it += 4) {
        float4 a = __ldg(p + (size_t)(it + 0) * stride);
        float4 b = __ldg(p + (size_t)(it + 1) * stride);
        float4 c = __ldg(p + (size_t)(it + 2) * stride);
        float4 d = __ldg(p + (size_t)(it + 3) * stride);
        s += fabsf(a.x) + fabsf(a.y) + fabsf(a.z) + fabsf(a.w);
        s += fabsf(b.x) + fabsf(b.y) + fabsf(b.z) + fabsf(b.w);
        s += fabsf(c.x) + fabsf(c.y) + fabsf(c.z) + fabsf(c.w);
        s += fabsf(d.x) + fabsf(d.y) + fabsf(d.z) + fabsf(d.w);
    }
#pragma unroll
    for (int off = 16; off; off >>= 1) s += __shfl_xor_sync(0xffffffffu, s, off);
    int lane = threadIdx.x & 31, w = threadIdx.x >> 5;
    if (lane == 0) sm[w] = s;
    __syncthreads();
    if (threadIdx.x == 0) {
        float tot = 0.f;
#pragma unroll
        for (int i = 0; i < 8; i++) tot += sm[i];
        g_bsum[blockIdx.x] = tot;
    }
}

// ---------------- kernel 3: finalize mean (unchanged, bit-exact) ----------------
__global__ void finalize_mean_kernel() {
    __shared__ float sm[8];
    int tid = threadIdx.x;
    float s = g_bsum[tid] + g_bsum[tid + 256] + g_bsum[tid + 512] + g_bsum[tid + 768];
#pragma unroll
    for (int off = 16; off; off >>= 1) s += __shfl_xor_sync(0xffffffffu, s, off);
    int lane = tid & 31, w = tid >> 5;
    if (lane == 0) sm[w] = s;
    __syncthreads();
    if (tid == 0) {
        float tot = 0.f;
#pragma unroll
        for (int i = 0; i < 8; i++) tot += sm[i];
        float mean = tot * (1.0f / 67108864.0f);
        float m = fmaxf(mean, 1e-5f);
        float s_w = __fdiv_rn(1.0f, m);
        float wdeq = __fdiv_rn(1.0f, s_w);
        g_wdeq = wdeq;
        g_thresh = 0.5f * wdeq;
    }
}

// ---------------- kernel 4: fused ternary GEMV, 3-stage cp.async pipeline ----------------
// Block: 64 rows x 2048-k chunk, 32 slices of 64 k, 3 smem buffers, ONE barrier/slice.
// Lane owns rows (lane, lane+32); 8 warps each own an 8-k lane of every slice.
__global__ void __launch_bounds__(256, 4) gemv_kernel(const float* __restrict__ W) {
    extern __shared__ float smem[];
    const float t = g_thresh;
    const int tid = threadIdx.x;
    const int lane = tid & 31, warp = tid >> 5;
    const int rt = blockIdx.x >> 2;            // 0..127 row tiles
    const int kc = blockIdx.x & 3;             // 0..3 k chunks
    const int rowbase = rt * ROWTILE;
    const int k0 = kc * CHUNK;
    const float* xt = (const float*)g_xt4;

    auto stage = [&](int s) {
        float* buf = smem + (s % NBUF) * BUF_FLOATS;
        float* bufX = buf + ROWTILE * SLICE_K;
        int base_k = k0 + s * SLICE_K;
#pragma unroll
        for (int i = 0; i < 4; i++) {
            int idx = tid + i * 256;           // 0..1023
            int r = idx >> 4, c = idx & 15;
            cpasync16(buf + r * SLICE_K + ((c ^ (r & 7)) << 2),
                      W + (size_t)(rowbase + r) * K_DIM + base_k + c * 4);
        }
        if (tid < 128) cpasync16(bufX + tid * 4, xt + (size_t)base_k * 8 + tid * 4);
    };

    ull a0 = 0, a1 = 0, a2 = 0, a3 = 0;
    ull b0 = 0, b1 = 0, b2 = 0, b3 = 0;

    stage(0); cp_commit();
    stage(1); cp_commit();

    const int sw = lane & 7;
    for (int s = 0; s < NSLICES; s++) {
        cp_wait1();                 // slice s group complete
        __syncthreads();            // data visible; compute(s-1) done block-wide
        if (s + 2 < NSLICES) stage(s + 2);
        cp_commit();

        const float* buf = smem + (s % NBUF) * BUF_FLOATS;
        const ulonglong2* Xb = (const ulonglong2*)(buf + ROWTILE * SLICE_K);
#pragma unroll
        for (int step = 0; step < 2; step++) {
            int kk = warp * 8 + step * 4;       // slice-local k
            int ch = kk >> 2;
            float4 wa = *(const float4*)(buf + lane * SLICE_K + ((ch ^ sw) << 2));
            float4 wb = *(const float4*)(buf + (lane + 32) * SLICE_K + ((ch ^ sw) << 2));
            float wae[4] = {wa.x, wa.y, wa.z, wa.w};
            float wbe[4] = {wb.x, wb.y, wb.z, wb.w};
#pragma unroll
            for (int e = 0; e < 4; e++) {
                ulonglong2 x0 = Xb[(kk + e) * 2];
                ulonglong2 x1 = Xb[(kk + e) * 2 + 1];
                ull qa = qpack(wae[e], t);
                ull qb = qpack(wbe[e], t);
                fma2(a0, x0.x, qa); fma2(a1, x0.y, qa);
                fma2(a2, x1.x, qa); fma2(a3, x1.y, qa);
                fma2(b0, x0.x, qb); fma2(b1, x0.y, qb);
                fma2(b2, x1.x, qb); fma2(b3, x1.y, qb);
            }
        }
    }

    // ---- in-block cross-warp reduction: 8 partials/row -> 1 ----
    __syncthreads();                // all compute done; smem reusable
    ulonglong2* s2 = (ulonglong2*)smem;
    s2[(warp * 64 + lane) * 2]          = make_ulonglong2(a0, a1);
    s2[(warp * 64 + lane) * 2 + 1]      = make_ulonglong2(a2, a3);
    s2[(warp * 64 + lane + 32) * 2]     = make_ulonglong2(b0, b1);
    s2[(warp * 64 + lane + 32) * 2 + 1] = make_ulonglong2(b2, b3);
    __syncthreads();
    if (tid < 64) {
        ull r0 = 0, r1 = 0, r2 = 0, r3 = 0;
#pragma unroll
        for (int w = 0; w < 8; w++) {
            ulonglong2 u0 = s2[(w * 64 + tid) * 2];
            ulonglong2 u1 = s2[(w * 64 + tid) * 2 + 1];
            add2(r0, u0.x); add2(r1, u0.y);
            add2(r2, u1.x); add2(r3, u1.y);
        }
        ulonglong2* P = (ulonglong2*)g_part;
        size_t p = ((size_t)(rowbase + tid) * KC + kc) * 2;
        P[p]     = make_ulonglong2(r0, r1);
        P[p + 1] = make_ulonglong2(r2, r3);
    }
}

// ---------------- kernel 5: reduce KC partials, apply w_deq ----------------
__global__ void finalize_out_kernel(float* __restrict__ out) {
    int m = blockIdx.x * blockDim.x + threadIdx.x;
    const float4* p = (const float4*)g_part + (size_t)m * KC * 2;
    float s0 = 0, s1 = 0, s2 = 0, s3 = 0, s4 = 0, s5 = 0, s6 = 0, s7 = 0;
#pragma unroll
    for (int ks = 0; ks < KC; ks++) {
        float4 A = p[ks * 2];
        float4 B = p[ks * 2 + 1];
        s0 += A.x; s1 += A.y; s2 += A.z; s3 += A.w;
        s4 += B.x; s5 += B.y; s6 += B.z; s7 += B.w;
    }
    float wd = g_wdeq;
    out[0 * M_DIM + m] = wd * s0;
    out[1 * M_DIM + m] = wd * s1;
    out[2 * M_DIM + m] = wd * s2;
    out[3 * M_DIM + m] = wd * s3;
    out[4 * M_DIM + m] = wd * s4;
    out[5 * M_DIM + m] = wd * s5;
    out[6 * M_DIM + m] = wd * s6;
    out[7 * M_DIM + m] = wd * s7;
}

// ---------------- launch ----------------
extern "C" void kernel_launch(void* const* d_in, const int* in_sizes, int n_in,
                              void* d_out, int out_size) {
    const float* x = (const float*)d_in[0];    // [8, 8192]
    const float* W = (const float*)d_in[1];    // [8192, 8192]
    float* out = (float*)d_out;                // [8, 8192]

    static bool attr_done = false;
    if (!attr_done) {
        cudaFuncSetAttribute(gemv_kernel, cudaFuncAttributeMaxDynamicSharedMemorySize,
                             SMEM_BYTES);
        attr_done = true;
    }

    quant_x_kernel<<<128, 256>>>(x);
    absmean_kernel<<<1024, 256>>>((const float4*)W);
    finalize_mean_kernel<<<1, 256>>>();
    gemv_kernel<<<512, 256, SMEM_BYTES>>>(W);
    finalize_out_kernel<<<64, 128>>>(out);
}